// round 10
// baseline (speedup 1.0000x reference)
#include <cuda_runtime.h>
#include <cuda_bf16.h>
#include <cstdint>
#include <math.h>

#define S_LEN 2048
#define HDIM  4096
#define NHEADS 32
#define NKVH   8
#define HEADD  128
#define KVDIM  1024

typedef __nv_bfloat16 bf16;

// ---------------- scratch (static device globals; no allocations) ----------
__device__ float g_q[S_LEN * HDIM];
__device__ float g_k[S_LEN * KVDIM];
__device__ float g_v[S_LEN * KVDIM];
__device__ float g_cos[S_LEN * 64];
__device__ float g_sin[S_LEN * 64];
// bf16 hi/lo panel-major planes (K -> panels of [R x 32])
__device__ bf16 g_xh[S_LEN * HDIM],  g_xl[S_LEN * HDIM];
__device__ bf16 g_wqh[HDIM * HDIM],  g_wql[HDIM * HDIM];
__device__ bf16 g_wkh[KVDIM * HDIM], g_wkl[KVDIM * HDIM];
__device__ bf16 g_wvh[KVDIM * HDIM], g_wvl[KVDIM * HDIM];
__device__ bf16 g_woh[HDIM * HDIM],  g_wol[HDIM * HDIM];
__device__ bf16 g_oh[S_LEN * HDIM],  g_ol[S_LEN * HDIM];

// ============================================================================
// helpers
// ============================================================================
__device__ __forceinline__ uint32_t smem_u32(const void* p) {
    uint32_t a;
    asm("{ .reg .u64 t; cvta.to.shared.u64 t, %1; cvt.u32.u64 %0, t; }"
        : "=r"(a) : "l"(p));
    return a;
}
__device__ __forceinline__ void ldmx4(uint32_t& r0, uint32_t& r1,
                                      uint32_t& r2, uint32_t& r3, uint32_t addr) {
    asm volatile("ldmatrix.sync.aligned.m8n8.x4.shared.b16 {%0,%1,%2,%3}, [%4];"
                 : "=r"(r0), "=r"(r1), "=r"(r2), "=r"(r3) : "r"(addr));
}
__device__ __forceinline__ void ldmx4t(uint32_t& r0, uint32_t& r1,
                                       uint32_t& r2, uint32_t& r3, uint32_t addr) {
    asm volatile("ldmatrix.sync.aligned.m8n8.x4.trans.shared.b16 {%0,%1,%2,%3}, [%4];"
                 : "=r"(r0), "=r"(r1), "=r"(r2), "=r"(r3) : "r"(addr));
}
__device__ __forceinline__ void mma16816(float* c, const uint32_t* a, const uint32_t* b) {
    asm volatile(
        "mma.sync.aligned.m16n8k16.row.col.f32.bf16.bf16.f32 "
        "{%0,%1,%2,%3}, {%4,%5,%6,%7}, {%8,%9}, {%0,%1,%2,%3};"
        : "+f"(c[0]), "+f"(c[1]), "+f"(c[2]), "+f"(c[3])
        : "r"(a[0]), "r"(a[1]), "r"(a[2]), "r"(a[3]), "r"(b[0]), "r"(b[1]));
}
__device__ __forceinline__ float ex2(float x) {
    float r;
    asm("ex2.approx.ftz.f32 %0, %1;" : "=f"(r) : "f"(x));
    return r;
}
__device__ __forceinline__ void split2(float x, float y, uint32_t& hi, uint32_t& lo) {
    bf16 hx = __float2bfloat16_rn(x);
    bf16 hy = __float2bfloat16_rn(y);
    bf16 lx = __float2bfloat16_rn(x - __bfloat162float(hx));
    bf16 ly = __float2bfloat16_rn(y - __bfloat162float(hy));
    __nv_bfloat162 H = {hx, hy}, L = {lx, ly};
    hi = *reinterpret_cast<uint32_t*>(&H);
    lo = *reinterpret_cast<uint32_t*>(&L);
}

// ============================================================================
// fp32 -> bf16 hi/lo, panel-major: plane[p*R*32 + r*32 + (k&31)], p = k>>5
// ============================================================================
__global__ __launch_bounds__(256) void convert_split(const float* __restrict__ src,
                                                     bf16* __restrict__ H,
                                                     bf16* __restrict__ L, int R)
{
    int idx = blockIdx.x * blockDim.x + threadIdx.x;
    if (idx >= R * 1024) return;
    int r = idx >> 10;
    int k4 = (idx & 1023) * 4;
    float4 v = *(const float4*)(src + (size_t)r * 4096 + k4);
    size_t off = (size_t)(k4 >> 5) * R * 32 + (size_t)r * 32 + (k4 & 31);
    uint32_t h0, l0, h1, l1;
    split2(v.x, v.y, h0, l0);
    split2(v.z, v.w, h1, l1);
    *(uint2*)(H + off) = make_uint2(h0, h1);
    *(uint2*)(L + off) = make_uint2(l0, l1);
}

// ============================================================================
// Pipelined bf16 split GEMM core (R7-proven: register prefetch, 1 CTA/SM).
// BM=BN=128, BK=32, 256 thr, double-buffered smem, stride-80 rows, 1 sync/iter.
// ============================================================================
#define PLSZ   10240                 // 128 rows * 80B
#define STAGESZ (4 * PLSZ)           // Ah, Al, Bh, Bl
#define GPIPE_SMEM (2 * STAGESZ)     // 81920

__device__ __forceinline__ void gemm_core(
    const bf16* __restrict__ Ahp, const bf16* __restrict__ Alp, int RA,
    const bf16* __restrict__ Bhp, const bf16* __restrict__ Blp, int RB,
    float* __restrict__ C, int Cs, int m0, int n0, char* sm)
{
    const uint32_t sb = smem_u32(sm);
    const int tid = threadIdx.x, lane = tid & 31, wid = tid >> 5;
    const int wr = wid >> 1, wc = wid & 1;

    // loader: 8 chunks of 16B per thread (2 per plane)
    const bf16* cur[8];
    uint32_t smoff[8];
    size_t pstr[8];
    {
        const bf16* gbase[4] = {Ahp + (size_t)m0 * 32, Alp + (size_t)m0 * 32,
                                Bhp + (size_t)n0 * 32, Blp + (size_t)n0 * 32};
        const size_t pstride[4] = {(size_t)RA * 32, (size_t)RA * 32,
                                   (size_t)RB * 32, (size_t)RB * 32};
#pragma unroll
        for (int j = 0; j < 8; j++) {
            int p = j >> 1;
            int cip = tid + 256 * (j & 1);
            cur[j] = gbase[p] + cip * 8;
            pstr[j] = pstride[p];
            smoff[j] = p * PLSZ + (cip >> 2) * 80 + (cip & 3) * 16;
        }
    }

    const uint32_t aA = sb + (wr * 32 + (lane & 15)) * 80 + ((lane >> 4) & 1) * 16;
    const uint32_t aB = sb + 2 * PLSZ +
        (wc * 64 + (lane & 7) + ((lane >> 4) & 1) * 8) * 80 + ((lane >> 3) & 1) * 16;

    float acc[2][8][4];
#pragma unroll
    for (int mt = 0; mt < 2; mt++)
#pragma unroll
        for (int nt = 0; nt < 8; nt++)
#pragma unroll
            for (int i = 0; i < 4; i++) acc[mt][nt][i] = 0.f;

    uint4 R[8];
#pragma unroll
    for (int j = 0; j < 8; j++) { R[j] = *(const uint4*)cur[j]; cur[j] += pstr[j]; }

    const int NK = 128;
    for (int it = 0; it < NK; ++it) {
        const uint32_t stg = (uint32_t)(it & 1) * STAGESZ;
        // STS staged chunk
#pragma unroll
        for (int j = 0; j < 8; j++)
            *(uint4*)(sm + stg + smoff[j]) = R[j];
        // prefetch next
        if (it + 1 < NK) {
#pragma unroll
            for (int j = 0; j < 8; j++) { R[j] = *(const uint4*)cur[j]; cur[j] += pstr[j]; }
        }
        __syncthreads();

#pragma unroll
        for (int ks = 0; ks < 2; ks++) {
            const uint32_t ko = stg + ks * 32;
            uint32_t Ah[2][4], Al[2][4];
#pragma unroll
            for (int mt = 0; mt < 2; mt++) {
                ldmx4(Ah[mt][0], Ah[mt][1], Ah[mt][2], Ah[mt][3], aA + ko + mt * 16 * 80);
                ldmx4(Al[mt][0], Al[mt][1], Al[mt][2], Al[mt][3],
                      aA + ko + PLSZ + mt * 16 * 80);
            }
#pragma unroll
            for (int np = 0; np < 4; np++) {
                uint32_t Bh[4], Bl[4];
                ldmx4(Bh[0], Bh[1], Bh[2], Bh[3], aB + ko + np * 16 * 80);
                ldmx4(Bl[0], Bl[1], Bl[2], Bl[3], aB + ko + PLSZ + np * 16 * 80);
#pragma unroll
                for (int mt = 0; mt < 2; mt++) {
                    mma16816(acc[mt][2*np],   Ah[mt], Bh);
                    mma16816(acc[mt][2*np],   Ah[mt], Bl);
                    mma16816(acc[mt][2*np],   Al[mt], Bh);
                    mma16816(acc[mt][2*np+1], Ah[mt], Bh + 2);
                    mma16816(acc[mt][2*np+1], Ah[mt], Bl + 2);
                    mma16816(acc[mt][2*np+1], Al[mt], Bh + 2);
                }
            }
        }
        // no second sync — next iter writes the other stage
    }

    const int gid = lane >> 2, tig = lane & 3;
#pragma unroll
    for (int mt = 0; mt < 2; mt++) {
        const int row = m0 + wr * 32 + mt * 16 + gid;
#pragma unroll
        for (int nt = 0; nt < 8; nt++) {
            const int col = n0 + wc * 64 + nt * 8 + tig * 2;
            *(float2*)(C + (size_t)row * Cs + col) =
                make_float2(acc[mt][nt][0], acc[mt][nt][1]);
            *(float2*)(C + (size_t)(row + 8) * Cs + col) =
                make_float2(acc[mt][nt][2], acc[mt][nt][3]);
        }
    }
}

__global__ __launch_bounds__(256) void gemm_qkv(float* __restrict__ qo,
                                                float* __restrict__ ko,
                                                float* __restrict__ vo)
{
    extern __shared__ char sm[];
    const int bx = blockIdx.x, by = blockIdx.y;
    const bf16 *Bh, *Bl; float* C; int Cs, RB, nb;
    if (bx < 32)      { Bh = g_wqh; Bl = g_wql; C = qo; Cs = 4096; RB = 4096; nb = bx; }
    else if (bx < 40) { Bh = g_wkh; Bl = g_wkl; C = ko; Cs = 1024; RB = 1024; nb = bx - 32; }
    else              { Bh = g_wvh; Bl = g_wvl; C = vo; Cs = 1024; RB = 1024; nb = bx - 40; }
    gemm_core(g_xh, g_xl, 2048, Bh, Bl, RB, C, Cs, by * 128, nb * 128, sm);
}

__global__ __launch_bounds__(256) void gemm_wo(float* __restrict__ out)
{
    extern __shared__ char sm[];
    gemm_core(g_oh, g_ol, 2048, g_woh, g_wol, 4096, out, 4096,
              blockIdx.y * 128, blockIdx.x * 128, sm);
}

// ---------------------------------------------------------------------------
// RoPE table (fp64, matches fp32 ref within 1 ulp)
// ---------------------------------------------------------------------------
__global__ void rope_table()
{
    int idx = blockIdx.x * blockDim.x + threadIdx.x;
    if (idx >= S_LEN * 64) return;
    int s = idx >> 6, i = idx & 63;
    double inv = pow(500000.0, -(double)i / 64.0);
    double a = (double)s * inv;
    g_cos[idx] = (float)cos(a);
    g_sin[idx] = (float)sin(a);
}

// ============================================================================
// Tensor-core flash attention with fused RoPE (Q & K) and bf16-panel output.
// Row-block schedule reversed for causal load balance. (R9-validated)
// ============================================================================
#define FRS 272
#define FQH 0
#define FQL (128 * FRS)
#define FKH (2 * 128 * FRS)
#define FKL (FKH + 64 * FRS)
#define FVH (FKH + 2 * 64 * FRS)
#define FVL (FKH + 3 * 64 * FRS)
#define FA2_SMEM (FKH + 4 * 64 * FRS)

__global__ __launch_bounds__(256) void flash_mma(const float* __restrict__ Q,
                                                 const float* __restrict__ K,
                                                 const float* __restrict__ V)
{
    extern __shared__ char sm[];
    const uint32_t sb = smem_u32(sm);
    const int tid = threadIdx.x, lane = tid & 31, wid = tid >> 5;
    const int h = blockIdx.y;
    const int bxr = (int)gridDim.x - 1 - (int)blockIdx.x;   // heavy blocks first
    const int m0 = bxr * 128;
    const int kvh = h >> 2;
    const float qscale = 0.0883883476483184f * 1.4426950408889634f;

    // ---- load Q + RoPE (pair exchange via shfl) + scale + split ----
    {
        int row = tid >> 1, half = tid & 1;
        const float* qp = Q + (size_t)(m0 + row) * HDIM + h * HEADD + half * 64;
        const float* cp = g_cos + (size_t)(m0 + row) * 64;
        const float* sp = g_sin + (size_t)(m0 + row) * 64;
        char* dh = sm + FQH + row * FRS + half * 128;
        char* dl = sm + FQL + row * FRS + half * 128;
        const float sgn = half ? 1.f : -1.f;
#pragma unroll
        for (int c = 0; c < 16; c++) {
            float4 v = ((const float4*)qp)[c];
            float4 cc = ((const float4*)cp)[c];
            float4 ss = ((const float4*)sp)[c];
            float4 pv;
            pv.x = __shfl_xor_sync(0xffffffffu, v.x, 1);
            pv.y = __shfl_xor_sync(0xffffffffu, v.y, 1);
            pv.z = __shfl_xor_sync(0xffffffffu, v.z, 1);
            pv.w = __shfl_xor_sync(0xffffffffu, v.w, 1);
            v.x = (v.x * cc.x + sgn * pv.x * ss.x) * qscale;
            v.y = (v.y * cc.y + sgn * pv.y * ss.y) * qscale;
            v.z = (v.z * cc.z + sgn * pv.z * ss.z) * qscale;
            v.w = (v.w * cc.w + sgn * pv.w * ss.w) * qscale;
            uint32_t h0, l0, h1, l1;
            split2(v.x, v.y, h0, l0);
            split2(v.z, v.w, h1, l1);
            ((uint2*)dh)[c] = make_uint2(h0, h1);
            ((uint2*)dl)[c] = make_uint2(l0, l1);
        }
    }

    float o[16][4];
#pragma unroll
    for (int dt = 0; dt < 16; dt++)
#pragma unroll
        for (int i = 0; i < 4; i++) o[dt][i] = 0.f;
    float mA = -1e30f, mB = -1e30f, lA = 0.f, lB = 0.f;

    const int wrow0 = m0 + wid * 16;
    const uint32_t aQh = sb + FQH + (wid * 16 + (lane & 15)) * FRS + ((lane >> 4) & 1) * 16;
    const uint32_t aQl = aQh + (FQL - FQH);
    const uint32_t kRow = (uint32_t)((lane & 7) + ((lane >> 4) & 1) * 8);
    const uint32_t kKo  = (uint32_t)(((lane >> 3) & 1) * 16);
    const uint32_t aKh = sb + FKH + kRow * FRS + kKo;
    const uint32_t aKl = aKh + (FKL - FKH);
    const uint32_t vRow = (uint32_t)((lane & 7) + ((lane >> 3) & 1) * 8);
    const uint32_t vDo  = (uint32_t)(((lane >> 4) & 1) * 16);
    const uint32_t aVh = sb + FVH + vRow * FRS + vDo;
    const uint32_t aVl = aVh + (FVL - FVH);

    const int jmax = 2 * bxr + 1;
    for (int j = 0; j <= jmax; j++) {
        const int n0 = j * 64;
        __syncthreads();
        // ---- load K (RoPE fused) / V ----
        {
            int row = tid >> 2, q = tid & 3;
            const float* kp = K + (size_t)(n0 + row) * KVDIM + kvh * HEADD + q * 32;
            const float* vp = V + (size_t)(n0 + row) * KVDIM + kvh * HEADD + q * 32;
            const float* cp = g_cos + (size_t)(n0 + row) * 64 + (q & 1) * 32;
            const float* sp = g_sin + (size_t)(n0 + row) * 64 + (q & 1) * 32;
            char* kh = sm + FKH + row * FRS + q * 64;
            char* kl = sm + FKL + row * FRS + q * 64;
            char* vh = sm + FVH + row * FRS + q * 64;
            char* vl = sm + FVL + row * FRS + q * 64;
            const float sgn = (q < 2) ? -1.f : 1.f;
#pragma unroll
            for (int c = 0; c < 8; c++) {
                float4 x = ((const float4*)kp)[c];
                float4 cc = ((const float4*)cp)[c];
                float4 ss = ((const float4*)sp)[c];
                float4 px;
                px.x = __shfl_xor_sync(0xffffffffu, x.x, 2);
                px.y = __shfl_xor_sync(0xffffffffu, x.y, 2);
                px.z = __shfl_xor_sync(0xffffffffu, x.z, 2);
                px.w = __shfl_xor_sync(0xffffffffu, x.w, 2);
                x.x = x.x * cc.x + sgn * px.x * ss.x;
                x.y = x.y * cc.y + sgn * px.y * ss.y;
                x.z = x.z * cc.z + sgn * px.z * ss.z;
                x.w = x.w * cc.w + sgn * px.w * ss.w;
                uint32_t h0, l0, h1, l1;
                split2(x.x, x.y, h0, l0);
                split2(x.z, x.w, h1, l1);
                ((uint2*)kh)[c] = make_uint2(h0, h1);
                ((uint2*)kl)[c] = make_uint2(l0, l1);
                x = ((const float4*)vp)[c];
                split2(x.x, x.y, h0, l0);
                split2(x.z, x.w, h1, l1);
                ((uint2*)vh)[c] = make_uint2(h0, h1);
                ((uint2*)vl)[c] = make_uint2(l0, l1);
            }
        }
        __syncthreads();

        if (n0 > wrow0 + 15) continue;

        float s[8][4];
#pragma unroll
        for (int t = 0; t < 8; t++)
#pragma unroll
            for (int i = 0; i < 4; i++) s[t][i] = 0.f;

#pragma unroll
        for (int kc = 0; kc < 8; kc++) {
            uint32_t qh[4], ql[4];
            ldmx4(qh[0], qh[1], qh[2], qh[3], aQh + kc * 32);
            ldmx4(ql[0], ql[1], ql[2], ql[3], aQl + kc * 32);
#pragma unroll
            for (int np = 0; np < 4; np++) {
                uint32_t kh[4], kl[4];
                ldmx4(kh[0], kh[1], kh[2], kh[3], aKh + np * 16 * FRS + kc * 32);
                ldmx4(kl[0], kl[1], kl[2], kl[3], aKl + np * 16 * FRS + kc * 32);
                mma16816(s[2*np],   qh, kh);
                mma16816(s[2*np],   qh, kl);
                mma16816(s[2*np],   ql, kh);
                mma16816(s[2*np+1], qh, kh + 2);
                mma16816(s[2*np+1], qh, kl + 2);
                mma16816(s[2*np+1], ql, kh + 2);
            }
        }

        const int rA = wrow0 + (lane >> 2);
        const int rB = rA + 8;
        const int cb = n0 + 2 * (lane & 3);
        if (n0 + 63 > wrow0) {
#pragma unroll
            for (int t = 0; t < 8; t++) {
                int c0 = cb + 8 * t;
                if (c0     > rA) s[t][0] = -1e30f;
                if (c0 + 1 > rA) s[t][1] = -1e30f;
                if (c0     > rB) s[t][2] = -1e30f;
                if (c0 + 1 > rB) s[t][3] = -1e30f;
            }
        }

        float xA = -1e30f, xB = -1e30f;
#pragma unroll
        for (int t = 0; t < 8; t++) {
            xA = fmaxf(xA, fmaxf(s[t][0], s[t][1]));
            xB = fmaxf(xB, fmaxf(s[t][2], s[t][3]));
        }
        xA = fmaxf(xA, __shfl_xor_sync(0xffffffffu, xA, 1));
        xA = fmaxf(xA, __shfl_xor_sync(0xffffffffu, xA, 2));
        xB = fmaxf(xB, __shfl_xor_sync(0xffffffffu, xB, 1));
        xB = fmaxf(xB, __shfl_xor_sync(0xffffffffu, xB, 2));
        float mAn = fmaxf(mA, xA), mBn = fmaxf(mB, xB);
        float cA = ex2(mA - mAn), cB = ex2(mB - mBn);
        mA = mAn; mB = mBn;
        float sumA = 0.f, sumB = 0.f;
#pragma unroll
        for (int t = 0; t < 8; t++) {
            s[t][0] = ex2(s[t][0] - mA); sumA += s[t][0];
            s[t][1] = ex2(s[t][1] - mA); sumA += s[t][1];
            s[t][2] = ex2(s[t][2] - mB); sumB += s[t][2];
            s[t][3] = ex2(s[t][3] - mB); sumB += s[t][3];
        }
        sumA += __shfl_xor_sync(0xffffffffu, sumA, 1);
        sumA += __shfl_xor_sync(0xffffffffu, sumA, 2);
        sumB += __shfl_xor_sync(0xffffffffu, sumB, 1);
        sumB += __shfl_xor_sync(0xffffffffu, sumB, 2);
        lA = lA * cA + sumA;
        lB = lB * cB + sumB;
#pragma unroll
        for (int dt = 0; dt < 16; dt++) {
            o[dt][0] *= cA; o[dt][1] *= cA;
            o[dt][2] *= cB; o[dt][3] *= cB;
        }

#pragma unroll
        for (int kc = 0; kc < 4; kc++) {
            uint32_t ph[4], pl[4];
            split2(s[2*kc][0],   s[2*kc][1],   ph[0], pl[0]);
            split2(s[2*kc][2],   s[2*kc][3],   ph[1], pl[1]);
            split2(s[2*kc+1][0], s[2*kc+1][1], ph[2], pl[2]);
            split2(s[2*kc+1][2], s[2*kc+1][3], ph[3], pl[3]);
#pragma unroll
            for (int dp = 0; dp < 8; dp++) {
                uint32_t vh[4], vl[4];
                ldmx4t(vh[0], vh[1], vh[2], vh[3], aVh + kc * 16 * FRS + dp * 32);
                ldmx4t(vl[0], vl[1], vl[2], vl[3], aVl + kc * 16 * FRS + dp * 32);
                mma16816(o[2*dp],   ph, vh);
                mma16816(o[2*dp],   ph, vl);
                mma16816(o[2*dp],   pl, vh);
                mma16816(o[2*dp+1], ph, vh + 2);
                mma16816(o[2*dp+1], ph, vl + 2);
                mma16816(o[2*dp+1], pl, vh + 2);
            }
        }
    }

    // ---- epilogue: normalized O -> bf16 hi/lo panel-major planes ----
    const float ilA = 1.f / lA, ilB = 1.f / lB;
    const int rA = wrow0 + (lane >> 2);
    const int colb = h * HEADD + 2 * (lane & 3);
#pragma unroll
    for (int dt = 0; dt < 16; dt++) {
        const int c = colb + 8 * dt;
        const size_t off  = (size_t)(c >> 5) * (S_LEN * 32) + (size_t)rA * 32 + (c & 31);
        const size_t off2 = off + 8 * 32;   // row rA+8
        uint32_t hi, lo;
        split2(o[dt][0] * ilA, o[dt][1] * ilA, hi, lo);
        *(uint32_t*)(g_oh + off) = hi;
        *(uint32_t*)(g_ol + off) = lo;
        split2(o[dt][2] * ilB, o[dt][3] * ilB, hi, lo);
        *(uint32_t*)(g_oh + off2) = hi;
        *(uint32_t*)(g_ol + off2) = lo;
    }
}

// ---------------------------------------------------------------------------
extern "C" void kernel_launch(void* const* d_in, const int* in_sizes, int n_in,
                              void* d_out, int out_size)
{
    const float* x  = (const float*)d_in[0];
    const float* wq = (const float*)d_in[1];
    const float* wk = (const float*)d_in[2];
    const float* wv = (const float*)d_in[3];
    const float* wo = (const float*)d_in[4];
    float* out = (float*)d_out;

    float *qb, *kb, *vb;
    cudaGetSymbolAddress((void**)&qb, g_q);
    cudaGetSymbolAddress((void**)&kb, g_k);
    cudaGetSymbolAddress((void**)&vb, g_v);
    bf16 *xh, *xl, *wqh, *wql, *wkh, *wkl, *wvh, *wvl, *woh, *wol;
    cudaGetSymbolAddress((void**)&xh,  g_xh);  cudaGetSymbolAddress((void**)&xl,  g_xl);
    cudaGetSymbolAddress((void**)&wqh, g_wqh); cudaGetSymbolAddress((void**)&wql, g_wql);
    cudaGetSymbolAddress((void**)&wkh, g_wkh); cudaGetSymbolAddress((void**)&wkl, g_wkl);
    cudaGetSymbolAddress((void**)&wvh, g_wvh); cudaGetSymbolAddress((void**)&wvl, g_wvl);
    cudaGetSymbolAddress((void**)&woh, g_woh); cudaGetSymbolAddress((void**)&wol, g_wol);

    cudaFuncSetAttribute(flash_mma, cudaFuncAttributeMaxDynamicSharedMemorySize, FA2_SMEM);
    cudaFuncSetAttribute(gemm_qkv,  cudaFuncAttributeMaxDynamicSharedMemorySize, GPIPE_SMEM);
    cudaFuncSetAttribute(gemm_wo,   cudaFuncAttributeMaxDynamicSharedMemorySize, GPIPE_SMEM);

    // RoPE table (independent of projections)
    rope_table<<<(S_LEN * 64) / 256, 256>>>();

    // preconvert inputs/weights to panel-major bf16 hi/lo
    convert_split<<<(2048 * 1024) / 256, 256>>>(x,  xh,  xl,  2048);
    convert_split<<<(4096 * 1024) / 256, 256>>>(wq, wqh, wql, 4096);
    convert_split<<<(1024 * 1024) / 256, 256>>>(wk, wkh, wkl, 1024);
    convert_split<<<(1024 * 1024) / 256, 256>>>(wv, wvh, wvl, 1024);
    convert_split<<<(4096 * 1024) / 256, 256>>>(wo, woh, wol, 4096);

    // fused QKV projection (R7-proven GEMM core)
    gemm_qkv<<<dim3(48, 16), 256, GPIPE_SMEM>>>(qb, kb, vb);

    // attention (RoPE fused into Q/K loads; writes bf16 hi/lo panels)
    flash_mma<<<dim3(S_LEN / 128, NHEADS), 256, FA2_SMEM>>>(qb, kb, vb);

    // output projection
    gemm_wo<<<dim3(32, 16), 256, GPIPE_SMEM>>>(out);
}

// round 11
// speedup vs baseline: 1.1494x; 1.1494x over previous
#include <cuda_runtime.h>
#include <cuda_bf16.h>
#include <cstdint>
#include <math.h>

#define S_LEN 2048
#define HDIM  4096
#define NHEADS 32
#define NKVH   8
#define HEADD  128
#define KVDIM  1024

typedef __nv_bfloat16 bf16;

// ---------------- scratch (static device globals; no allocations) ----------
__device__ float g_q[S_LEN * HDIM];
__device__ float g_k[S_LEN * KVDIM];
__device__ float g_v[S_LEN * KVDIM];
__device__ float g_o[S_LEN * HDIM];
__device__ float g_cos[S_LEN * 64];
__device__ float g_sin[S_LEN * 64];
// bf16 hi/lo panel-major planes (K -> panels of [R x 32])
__device__ bf16 g_xh[S_LEN * HDIM],  g_xl[S_LEN * HDIM];
__device__ bf16 g_wqh[HDIM * HDIM],  g_wql[HDIM * HDIM];
__device__ bf16 g_wkh[KVDIM * HDIM], g_wkl[KVDIM * HDIM];
__device__ bf16 g_wvh[KVDIM * HDIM], g_wvl[KVDIM * HDIM];
__device__ bf16 g_woh[HDIM * HDIM],  g_wol[HDIM * HDIM];
__device__ bf16 g_oh[S_LEN * HDIM],  g_ol[S_LEN * HDIM];
// pre-formatted KV tiles: [kvh][j][4 planes: Kh,Kl,Vh,Vl][64 rows x 272B]
#define PL      17408                 // 64 * 272
#define TILESZ  (4 * PL)              // 69632
__device__ uint4 g_kvt[(NKVH * 32 * TILESZ) / 16];

// ============================================================================
// helpers
// ============================================================================
__device__ __forceinline__ uint32_t smem_u32(const void* p) {
    uint32_t a;
    asm("{ .reg .u64 t; cvta.to.shared.u64 t, %1; cvt.u32.u64 %0, t; }"
        : "=r"(a) : "l"(p));
    return a;
}
__device__ __forceinline__ void ldmx4(uint32_t& r0, uint32_t& r1,
                                      uint32_t& r2, uint32_t& r3, uint32_t addr) {
    asm volatile("ldmatrix.sync.aligned.m8n8.x4.shared.b16 {%0,%1,%2,%3}, [%4];"
                 : "=r"(r0), "=r"(r1), "=r"(r2), "=r"(r3) : "r"(addr));
}
__device__ __forceinline__ void ldmx4t(uint32_t& r0, uint32_t& r1,
                                       uint32_t& r2, uint32_t& r3, uint32_t addr) {
    asm volatile("ldmatrix.sync.aligned.m8n8.x4.trans.shared.b16 {%0,%1,%2,%3}, [%4];"
                 : "=r"(r0), "=r"(r1), "=r"(r2), "=r"(r3) : "r"(addr));
}
__device__ __forceinline__ void mma16816(float* c, const uint32_t* a, const uint32_t* b) {
    asm volatile(
        "mma.sync.aligned.m16n8k16.row.col.f32.bf16.bf16.f32 "
        "{%0,%1,%2,%3}, {%4,%5,%6,%7}, {%8,%9}, {%0,%1,%2,%3};"
        : "+f"(c[0]), "+f"(c[1]), "+f"(c[2]), "+f"(c[3])
        : "r"(a[0]), "r"(a[1]), "r"(a[2]), "r"(a[3]), "r"(b[0]), "r"(b[1]));
}
__device__ __forceinline__ float ex2(float x) {
    float r;
    asm("ex2.approx.ftz.f32 %0, %1;" : "=f"(r) : "f"(x));
    return r;
}
__device__ __forceinline__ void split2(float x, float y, uint32_t& hi, uint32_t& lo) {
    bf16 hx = __float2bfloat16_rn(x);
    bf16 hy = __float2bfloat16_rn(y);
    bf16 lx = __float2bfloat16_rn(x - __bfloat162float(hx));
    bf16 ly = __float2bfloat16_rn(y - __bfloat162float(hy));
    __nv_bfloat162 H = {hx, hy}, L = {lx, ly};
    hi = *reinterpret_cast<uint32_t*>(&H);
    lo = *reinterpret_cast<uint32_t*>(&L);
}
__device__ __forceinline__ void cp16(uint32_t smem_dst, const void* gsrc) {
    asm volatile("cp.async.cg.shared.global [%0], [%1], 16;"
                 :: "r"(smem_dst), "l"(gsrc) : "memory");
}
#define CP_COMMIT() asm volatile("cp.async.commit_group;" ::: "memory")
#define CP_WAIT0()  asm volatile("cp.async.wait_group 0;" ::: "memory")

// ============================================================================
// fp32 -> bf16 hi/lo, panel-major: plane[p*R*32 + r*32 + (k&31)], p = k>>5
// ============================================================================
__global__ __launch_bounds__(256) void convert_split(const float* __restrict__ src,
                                                     bf16* __restrict__ H,
                                                     bf16* __restrict__ L, int R)
{
    int idx = blockIdx.x * blockDim.x + threadIdx.x;
    if (idx >= R * 1024) return;
    int r = idx >> 10;
    int k4 = (idx & 1023) * 4;
    float4 v = *(const float4*)(src + (size_t)r * 4096 + k4);
    size_t off = (size_t)(k4 >> 5) * R * 32 + (size_t)r * 32 + (k4 & 31);
    uint32_t h0, l0, h1, l1;
    split2(v.x, v.y, h0, l0);
    split2(v.z, v.w, h1, l1);
    *(uint2*)(H + off) = make_uint2(h0, h1);
    *(uint2*)(L + off) = make_uint2(l0, l1);
}

// ============================================================================
// cp.async double-buffered bf16 split GEMM (R9-measured-best core).
// ============================================================================
#define PLSZ   10240
#define STAGESZ (4 * PLSZ)
#define GPIPE_SMEM (2 * STAGESZ)

__device__ __forceinline__ void gemm_core(
    const bf16* __restrict__ Ahp, const bf16* __restrict__ Alp, int RA,
    const bf16* __restrict__ Bhp, const bf16* __restrict__ Blp, int RB,
    float* __restrict__ C, int Cs, int m0, int n0, char* sm)
{
    const uint32_t sb = smem_u32(sm);
    const int tid = threadIdx.x, lane = tid & 31, wid = tid >> 5;
    const int wr = wid >> 1, wc = wid & 1;

    const bf16* cur[8];
    uint32_t smoff[8];
    size_t pstr[8];
    {
        const bf16* gbase[4] = {Ahp + (size_t)m0 * 32, Alp + (size_t)m0 * 32,
                                Bhp + (size_t)n0 * 32, Blp + (size_t)n0 * 32};
        const size_t pstride[4] = {(size_t)RA * 32, (size_t)RA * 32,
                                   (size_t)RB * 32, (size_t)RB * 32};
#pragma unroll
        for (int j = 0; j < 8; j++) {
            int p = j >> 1;
            int cip = tid + 256 * (j & 1);
            cur[j] = gbase[p] + cip * 8;
            pstr[j] = pstride[p];
            smoff[j] = p * PLSZ + (cip >> 2) * 80 + (cip & 3) * 16;
        }
    }

    const uint32_t aA = sb + (wr * 32 + (lane & 15)) * 80 + ((lane >> 4) & 1) * 16;
    const uint32_t aB = sb + 2 * PLSZ +
        (wc * 64 + (lane & 7) + ((lane >> 4) & 1) * 8) * 80 + ((lane >> 3) & 1) * 16;

    float acc[2][8][4];
#pragma unroll
    for (int mt = 0; mt < 2; mt++)
#pragma unroll
        for (int nt = 0; nt < 8; nt++)
#pragma unroll
            for (int i = 0; i < 4; i++) acc[mt][nt][i] = 0.f;

#pragma unroll
    for (int j = 0; j < 8; j++) { cp16(sb + smoff[j], cur[j]); cur[j] += pstr[j]; }
    CP_COMMIT();

    const int NK = 128;
    for (int it = 0; it < NK; ++it) {
        const uint32_t stg = (uint32_t)(it & 1) * STAGESZ;
        CP_WAIT0();
        __syncthreads();
        if (it + 1 < NK) {
            const uint32_t nstg = (uint32_t)((it + 1) & 1) * STAGESZ;
#pragma unroll
            for (int j = 0; j < 8; j++) { cp16(sb + nstg + smoff[j], cur[j]); cur[j] += pstr[j]; }
            CP_COMMIT();
        }

#pragma unroll
        for (int ks = 0; ks < 2; ks++) {
            const uint32_t ko = stg + ks * 32;
            uint32_t Ah[2][4], Al[2][4];
#pragma unroll
            for (int mt = 0; mt < 2; mt++) {
                ldmx4(Ah[mt][0], Ah[mt][1], Ah[mt][2], Ah[mt][3], aA + ko + mt * 16 * 80);
                ldmx4(Al[mt][0], Al[mt][1], Al[mt][2], Al[mt][3],
                      aA + ko + PLSZ + mt * 16 * 80);
            }
#pragma unroll
            for (int np = 0; np < 4; np++) {
                uint32_t Bh[4], Bl[4];
                ldmx4(Bh[0], Bh[1], Bh[2], Bh[3], aB + ko + np * 16 * 80);
                ldmx4(Bl[0], Bl[1], Bl[2], Bl[3], aB + ko + PLSZ + np * 16 * 80);
#pragma unroll
                for (int mt = 0; mt < 2; mt++) {
                    mma16816(acc[mt][2*np],   Ah[mt], Bh);
                    mma16816(acc[mt][2*np],   Ah[mt], Bl);
                    mma16816(acc[mt][2*np],   Al[mt], Bh);
                    mma16816(acc[mt][2*np+1], Ah[mt], Bh + 2);
                    mma16816(acc[mt][2*np+1], Ah[mt], Bl + 2);
                    mma16816(acc[mt][2*np+1], Al[mt], Bh + 2);
                }
            }
        }
    }

    const int gid = lane >> 2, tig = lane & 3;
#pragma unroll
    for (int mt = 0; mt < 2; mt++) {
        const int row = m0 + wr * 32 + mt * 16 + gid;
#pragma unroll
        for (int nt = 0; nt < 8; nt++) {
            const int col = n0 + wc * 64 + nt * 8 + tig * 2;
            *(float2*)(C + (size_t)row * Cs + col) =
                make_float2(acc[mt][nt][0], acc[mt][nt][1]);
            *(float2*)(C + (size_t)(row + 8) * Cs + col) =
                make_float2(acc[mt][nt][2], acc[mt][nt][3]);
        }
    }
}

__global__ __launch_bounds__(256, 2) void gemm_qkv(float* __restrict__ qo,
                                                   float* __restrict__ ko,
                                                   float* __restrict__ vo)
{
    extern __shared__ char sm[];
    const int bx = blockIdx.x, by = blockIdx.y;
    const bf16 *Bh, *Bl; float* C; int Cs, RB, nb;
    if (bx < 32)      { Bh = g_wqh; Bl = g_wql; C = qo; Cs = 4096; RB = 4096; nb = bx; }
    else if (bx < 40) { Bh = g_wkh; Bl = g_wkl; C = ko; Cs = 1024; RB = 1024; nb = bx - 32; }
    else              { Bh = g_wvh; Bl = g_wvl; C = vo; Cs = 1024; RB = 1024; nb = bx - 40; }
    gemm_core(g_xh, g_xl, 2048, Bh, Bl, RB, C, Cs, by * 128, nb * 128, sm);
}

__global__ __launch_bounds__(256, 2) void gemm_wo(float* __restrict__ out)
{
    extern __shared__ char sm[];
    gemm_core(g_oh, g_ol, 2048, g_woh, g_wol, 4096, out, 4096,
              blockIdx.y * 128, blockIdx.x * 128, sm);
}

// ---------------------------------------------------------------------------
// RoPE table + apply (Q only; K's RoPE moves into kv_prep)
// ---------------------------------------------------------------------------
__global__ void rope_table()
{
    int idx = blockIdx.x * blockDim.x + threadIdx.x;
    if (idx >= S_LEN * 64) return;
    int s = idx >> 6, i = idx & 63;
    double inv = pow(500000.0, -(double)i / 64.0);
    double a = (double)s * inv;
    g_cos[idx] = (float)cos(a);
    g_sin[idx] = (float)sin(a);
}
__global__ void rope_apply(float* __restrict__ buf, int nheads)
{
    int idx = blockIdx.x * blockDim.x + threadIdx.x;
    int total = S_LEN * nheads * 64;
    if (idx >= total) return;
    int i = idx & 63;
    int h = (idx >> 6) % nheads;
    int s = idx / (nheads * 64);
    float c  = g_cos[s * 64 + i];
    float sn = g_sin[s * 64 + i];
    float* p = buf + (size_t)s * nheads * HEADD + h * HEADD;
    float x0 = p[i];
    float x1 = p[i + 64];
    p[i]      = x0 * c - x1 * sn;
    p[i + 64] = x1 * c + x0 * sn;
}

// ============================================================================
// kv_prep: K (RoPE'd) + V -> bf16 hi/lo smem-image tiles in gmem.
// 65536 threads: t -> q=t&3 (32-dim chunk), kvh=(t>>2)&7, s=t>>5.
// ============================================================================
__global__ __launch_bounds__(256) void kv_prep()
{
    int t = blockIdx.x * 256 + threadIdx.x;
    int q = t & 3, kvh = (t >> 2) & 7, s = t >> 5;
    const float* kp = g_k + (size_t)s * KVDIM + kvh * HEADD + q * 32;
    const float* pp = g_k + (size_t)s * KVDIM + kvh * HEADD + (q ^ 2) * 32;
    const float* vp = g_v + (size_t)s * KVDIM + kvh * HEADD + q * 32;
    const float* cp_ = g_cos + (size_t)s * 64 + (q & 1) * 32;
    const float* sp_ = g_sin + (size_t)s * 64 + (q & 1) * 32;
    const float sgn = (q < 2) ? -1.f : 1.f;
    const int j = s >> 6, r = s & 63;
    char* tb = (char*)g_kvt + (size_t)(kvh * 32 + j) * TILESZ + r * 272 + q * 64;
    char* kh = tb;
    char* kl = tb + PL;
    char* vh = tb + 2 * PL;
    char* vl = tb + 3 * PL;
#pragma unroll
    for (int c = 0; c < 8; c++) {
        float4 x  = ((const float4*)kp)[c];
        float4 px = ((const float4*)pp)[c];
        float4 cc = ((const float4*)cp_)[c];
        float4 sv = ((const float4*)sp_)[c];
        x.x = x.x * cc.x + sgn * px.x * sv.x;
        x.y = x.y * cc.y + sgn * px.y * sv.y;
        x.z = x.z * cc.z + sgn * px.z * sv.z;
        x.w = x.w * cc.w + sgn * px.w * sv.w;
        uint32_t h0, l0, h1, l1;
        split2(x.x, x.y, h0, l0);
        split2(x.z, x.w, h1, l1);
        ((uint2*)kh)[c] = make_uint2(h0, h1);
        ((uint2*)kl)[c] = make_uint2(l0, l1);
        x = ((const float4*)vp)[c];
        split2(x.x, x.y, h0, l0);
        split2(x.z, x.w, h1, l1);
        ((uint2*)vh)[c] = make_uint2(h0, h1);
        ((uint2*)vl)[c] = make_uint2(l0, l1);
    }
}

// ============================================================================
// Tensor-core flash attention: Q fp32 load+scale+split (proven), KV via
// cp.async double-buffer from pre-formatted tiles. fp32 O out (proven).
// ============================================================================
#define FQHo 0
#define FQLo 34816
#define SKV0 69632
#define FA3_SMEM (69632 + 2 * TILESZ)    // 208896

__global__ __launch_bounds__(256) void flash_mma(const float* __restrict__ Q,
                                                 float* __restrict__ O)
{
    extern __shared__ char sm[];
    const uint32_t sb = smem_u32(sm);
    const int tid = threadIdx.x, lane = tid & 31, wid = tid >> 5;
    const int h = blockIdx.y;
    const int bxr = (int)gridDim.x - 1 - (int)blockIdx.x;   // heavy blocks first
    const int m0 = bxr * 128;
    const int kvh = h >> 2;
    const float qscale = 0.0883883476483184f * 1.4426950408889634f;

    // ---- load Q (scaled, split) ----
    {
        int row = tid >> 1, half = tid & 1;
        const float* qp = Q + (size_t)(m0 + row) * HDIM + h * HEADD + half * 64;
        char* dh = sm + FQHo + row * 272 + half * 128;
        char* dl = sm + FQLo + row * 272 + half * 128;
#pragma unroll
        for (int c = 0; c < 16; c++) {
            float4 v = ((const float4*)qp)[c];
            v.x *= qscale; v.y *= qscale; v.z *= qscale; v.w *= qscale;
            uint32_t h0, l0, h1, l1;
            split2(v.x, v.y, h0, l0);
            split2(v.z, v.w, h1, l1);
            ((uint2*)dh)[c] = make_uint2(h0, h1);
            ((uint2*)dl)[c] = make_uint2(l0, l1);
        }
    }

    float o[16][4];
#pragma unroll
    for (int dt = 0; dt < 16; dt++)
#pragma unroll
        for (int i = 0; i < 4; i++) o[dt][i] = 0.f;
    float mA = -1e30f, mB = -1e30f, lA = 0.f, lB = 0.f;

    const int wrow0 = m0 + wid * 16;
    const uint32_t aQh = sb + FQHo + (wid * 16 + (lane & 15)) * 272 + ((lane >> 4) & 1) * 16;
    const uint32_t aQl = aQh + (FQLo - FQHo);
    const uint32_t relK = ((lane & 7) + ((lane >> 4) & 1) * 8) * 272 + ((lane >> 3) & 1) * 16;
    const uint32_t relV = ((lane & 7) + ((lane >> 3) & 1) * 8) * 272 + ((lane >> 4) & 1) * 16;

    const char* blob = (const char*)g_kvt + (size_t)(kvh * 32) * TILESZ;
    const int jmax = 2 * bxr + 1;

    // prologue: copy tile 0 into stage 0
    {
        const char* src = blob + tid * 16;
        const uint32_t dst = sb + SKV0 + tid * 16;
#pragma unroll
        for (int i = 0; i < 17; i++) cp16(dst + i * 4096, src + i * 4096);
        CP_COMMIT();
    }

    for (int j = 0; j <= jmax; j++) {
        const int n0 = j * 64;
        const uint32_t stg = SKV0 + (uint32_t)(j & 1) * TILESZ;
        CP_WAIT0();
        __syncthreads();
        // prefetch next tile into the other stage (overlaps compute)
        if (j + 1 <= jmax) {
            const char* src = blob + (size_t)(j + 1) * TILESZ + tid * 16;
            const uint32_t dst = sb + SKV0 + (uint32_t)((j + 1) & 1) * TILESZ + tid * 16;
#pragma unroll
            for (int i = 0; i < 17; i++) cp16(dst + i * 4096, src + i * 4096);
            CP_COMMIT();
        }

        if (n0 > wrow0 + 15) continue;   // fully masked for this warp

        const uint32_t aKh = sb + stg + relK;
        const uint32_t aKl = aKh + PL;
        const uint32_t aVh = sb + stg + 2 * PL + relV;
        const uint32_t aVl = aVh + PL;

        float s[8][4];
#pragma unroll
        for (int t = 0; t < 8; t++)
#pragma unroll
            for (int i = 0; i < 4; i++) s[t][i] = 0.f;

#pragma unroll
        for (int kc = 0; kc < 8; kc++) {
            uint32_t qh[4], ql[4];
            ldmx4(qh[0], qh[1], qh[2], qh[3], aQh + kc * 32);
            ldmx4(ql[0], ql[1], ql[2], ql[3], aQl + kc * 32);
#pragma unroll
            for (int np = 0; np < 4; np++) {
                uint32_t kh[4], kl[4];
                ldmx4(kh[0], kh[1], kh[2], kh[3], aKh + np * 16 * 272 + kc * 32);
                ldmx4(kl[0], kl[1], kl[2], kl[3], aKl + np * 16 * 272 + kc * 32);
                mma16816(s[2*np],   qh, kh);
                mma16816(s[2*np],   qh, kl);
                mma16816(s[2*np],   ql, kh);
                mma16816(s[2*np+1], qh, kh + 2);
                mma16816(s[2*np+1], qh, kl + 2);
                mma16816(s[2*np+1], ql, kh + 2);
            }
        }

        const int rA = wrow0 + (lane >> 2);
        const int rB = rA + 8;
        const int cb = n0 + 2 * (lane & 3);
        if (n0 + 63 > wrow0) {
#pragma unroll
            for (int t = 0; t < 8; t++) {
                int c0 = cb + 8 * t;
                if (c0     > rA) s[t][0] = -1e30f;
                if (c0 + 1 > rA) s[t][1] = -1e30f;
                if (c0     > rB) s[t][2] = -1e30f;
                if (c0 + 1 > rB) s[t][3] = -1e30f;
            }
        }

        float xA = -1e30f, xB = -1e30f;
#pragma unroll
        for (int t = 0; t < 8; t++) {
            xA = fmaxf(xA, fmaxf(s[t][0], s[t][1]));
            xB = fmaxf(xB, fmaxf(s[t][2], s[t][3]));
        }
        xA = fmaxf(xA, __shfl_xor_sync(0xffffffffu, xA, 1));
        xA = fmaxf(xA, __shfl_xor_sync(0xffffffffu, xA, 2));
        xB = fmaxf(xB, __shfl_xor_sync(0xffffffffu, xB, 1));
        xB = fmaxf(xB, __shfl_xor_sync(0xffffffffu, xB, 2));
        float mAn = fmaxf(mA, xA), mBn = fmaxf(mB, xB);
        float cA = ex2(mA - mAn), cB = ex2(mB - mBn);
        mA = mAn; mB = mBn;
        float sumA = 0.f, sumB = 0.f;
#pragma unroll
        for (int t = 0; t < 8; t++) {
            s[t][0] = ex2(s[t][0] - mA); sumA += s[t][0];
            s[t][1] = ex2(s[t][1] - mA); sumA += s[t][1];
            s[t][2] = ex2(s[t][2] - mB); sumB += s[t][2];
            s[t][3] = ex2(s[t][3] - mB); sumB += s[t][3];
        }
        sumA += __shfl_xor_sync(0xffffffffu, sumA, 1);
        sumA += __shfl_xor_sync(0xffffffffu, sumA, 2);
        sumB += __shfl_xor_sync(0xffffffffu, sumB, 1);
        sumB += __shfl_xor_sync(0xffffffffu, sumB, 2);
        lA = lA * cA + sumA;
        lB = lB * cB + sumB;
#pragma unroll
        for (int dt = 0; dt < 16; dt++) {
            o[dt][0] *= cA; o[dt][1] *= cA;
            o[dt][2] *= cB; o[dt][3] *= cB;
        }

#pragma unroll
        for (int kc = 0; kc < 4; kc++) {
            uint32_t ph[4], pl[4];
            split2(s[2*kc][0],   s[2*kc][1],   ph[0], pl[0]);
            split2(s[2*kc][2],   s[2*kc][3],   ph[1], pl[1]);
            split2(s[2*kc+1][0], s[2*kc+1][1], ph[2], pl[2]);
            split2(s[2*kc+1][2], s[2*kc+1][3], ph[3], pl[3]);
#pragma unroll
            for (int dp = 0; dp < 8; dp++) {
                uint32_t vh[4], vl[4];
                ldmx4t(vh[0], vh[1], vh[2], vh[3], aVh + kc * 16 * 272 + dp * 32);
                ldmx4t(vl[0], vl[1], vl[2], vl[3], aVl + kc * 16 * 272 + dp * 32);
                mma16816(o[2*dp],   ph, vh);
                mma16816(o[2*dp],   ph, vl);
                mma16816(o[2*dp],   pl, vh);
                mma16816(o[2*dp+1], ph, vh + 2);
                mma16816(o[2*dp+1], ph, vl + 2);
                mma16816(o[2*dp+1], pl, vh + 2);
            }
        }
    }

    // ---- epilogue: fp32 O (proven coalesced path) ----
    const float ilA = 1.f / lA, ilB = 1.f / lB;
    const int rA = wrow0 + (lane >> 2);
    const int colb = h * HEADD + 2 * (lane & 3);
#pragma unroll
    for (int dt = 0; dt < 16; dt++) {
        *(float2*)(O + (size_t)rA * HDIM + colb + 8 * dt) =
            make_float2(o[dt][0] * ilA, o[dt][1] * ilA);
        *(float2*)(O + (size_t)(rA + 8) * HDIM + colb + 8 * dt) =
            make_float2(o[dt][2] * ilB, o[dt][3] * ilB);
    }
}

// ---------------------------------------------------------------------------
extern "C" void kernel_launch(void* const* d_in, const int* in_sizes, int n_in,
                              void* d_out, int out_size)
{
    const float* x  = (const float*)d_in[0];
    const float* wq = (const float*)d_in[1];
    const float* wk = (const float*)d_in[2];
    const float* wv = (const float*)d_in[3];
    const float* wo = (const float*)d_in[4];
    float* out = (float*)d_out;

    float *qb, *kb, *vb, *ob;
    cudaGetSymbolAddress((void**)&qb, g_q);
    cudaGetSymbolAddress((void**)&kb, g_k);
    cudaGetSymbolAddress((void**)&vb, g_v);
    cudaGetSymbolAddress((void**)&ob, g_o);
    bf16 *xh, *xl, *wqh, *wql, *wkh, *wkl, *wvh, *wvl, *woh, *wol, *oh, *ol;
    cudaGetSymbolAddress((void**)&xh,  g_xh);  cudaGetSymbolAddress((void**)&xl,  g_xl);
    cudaGetSymbolAddress((void**)&wqh, g_wqh); cudaGetSymbolAddress((void**)&wql, g_wql);
    cudaGetSymbolAddress((void**)&wkh, g_wkh); cudaGetSymbolAddress((void**)&wkl, g_wkl);
    cudaGetSymbolAddress((void**)&wvh, g_wvh); cudaGetSymbolAddress((void**)&wvl, g_wvl);
    cudaGetSymbolAddress((void**)&woh, g_woh); cudaGetSymbolAddress((void**)&wol, g_wol);
    cudaGetSymbolAddress((void**)&oh,  g_oh);  cudaGetSymbolAddress((void**)&ol,  g_ol);

    cudaFuncSetAttribute(flash_mma, cudaFuncAttributeMaxDynamicSharedMemorySize, FA3_SMEM);
    cudaFuncSetAttribute(gemm_qkv,  cudaFuncAttributeMaxDynamicSharedMemorySize, GPIPE_SMEM);
    cudaFuncSetAttribute(gemm_wo,   cudaFuncAttributeMaxDynamicSharedMemorySize, GPIPE_SMEM);

    // RoPE table (independent)
    rope_table<<<(S_LEN * 64) / 256, 256>>>();

    // preconvert inputs/weights
    convert_split<<<(2048 * 1024) / 256, 256>>>(x,  xh,  xl,  2048);
    convert_split<<<(4096 * 1024) / 256, 256>>>(wq, wqh, wql, 4096);
    convert_split<<<(1024 * 1024) / 256, 256>>>(wk, wkh, wkl, 1024);
    convert_split<<<(1024 * 1024) / 256, 256>>>(wv, wvh, wvl, 1024);
    convert_split<<<(4096 * 1024) / 256, 256>>>(wo, woh, wol, 4096);

    // fused QKV projection (cp.async core)
    gemm_qkv<<<dim3(48, 16), 256, GPIPE_SMEM>>>(qb, kb, vb);

    // RoPE on Q; K RoPE + KV split/tiling in kv_prep
    rope_apply<<<(S_LEN * NHEADS * 64) / 256, 256>>>(qb, NHEADS);
    kv_prep<<<256, 256>>>();

    // attention (KV via cp.async from pre-formatted tiles)
    flash_mma<<<dim3(S_LEN / 128, NHEADS), 256, FA3_SMEM>>>(qb, ob);

    // output projection
    convert_split<<<(2048 * 1024) / 256, 256>>>(ob, oh, ol, 2048);
    gemm_wo<<<dim3(32, 16), 256, GPIPE_SMEM>>>(out);
}

// round 12
// speedup vs baseline: 1.1686x; 1.0167x over previous
#include <cuda_runtime.h>
#include <cuda_bf16.h>
#include <cstdint>
#include <math.h>

#define S_LEN 2048
#define HDIM  4096
#define NHEADS 32
#define NKVH   8
#define HEADD  128
#define KVDIM  1024

typedef __nv_bfloat16 bf16;

// ---------------- scratch (static device globals; no allocations) ----------
__device__ float g_q[S_LEN * HDIM];
__device__ float g_k[S_LEN * KVDIM];
__device__ float g_v[S_LEN * KVDIM];
__device__ float g_o[S_LEN * HDIM];
__device__ float g_cos[S_LEN * 64];
__device__ float g_sin[S_LEN * 64];
// bf16 hi/lo panel-major planes (K -> panels of [R x 32])
__device__ bf16 g_xh[S_LEN * HDIM],  g_xl[S_LEN * HDIM];
__device__ bf16 g_wqh[HDIM * HDIM],  g_wql[HDIM * HDIM];
__device__ bf16 g_wkh[KVDIM * HDIM], g_wkl[KVDIM * HDIM];
__device__ bf16 g_wvh[KVDIM * HDIM], g_wvl[KVDIM * HDIM];
__device__ bf16 g_woh[HDIM * HDIM],  g_wol[HDIM * HDIM];
__device__ bf16 g_oh[S_LEN * HDIM],  g_ol[S_LEN * HDIM];
// pre-formatted KV tiles: [kvh][j][4 planes: Kh,Kl,Vh,Vl][64 rows x 272B]
#define PL      17408                 // 64 * 272
#define TILESZ  (4 * PL)              // 69632
__device__ uint4 g_kvt[(NKVH * 32 * TILESZ) / 16];

// ============================================================================
// helpers
// ============================================================================
__device__ __forceinline__ uint32_t smem_u32(const void* p) {
    uint32_t a;
    asm("{ .reg .u64 t; cvta.to.shared.u64 t, %1; cvt.u32.u64 %0, t; }"
        : "=r"(a) : "l"(p));
    return a;
}
__device__ __forceinline__ void ldmx4(uint32_t& r0, uint32_t& r1,
                                      uint32_t& r2, uint32_t& r3, uint32_t addr) {
    asm volatile("ldmatrix.sync.aligned.m8n8.x4.shared.b16 {%0,%1,%2,%3}, [%4];"
                 : "=r"(r0), "=r"(r1), "=r"(r2), "=r"(r3) : "r"(addr));
}
__device__ __forceinline__ void ldmx4t(uint32_t& r0, uint32_t& r1,
                                       uint32_t& r2, uint32_t& r3, uint32_t addr) {
    asm volatile("ldmatrix.sync.aligned.m8n8.x4.trans.shared.b16 {%0,%1,%2,%3}, [%4];"
                 : "=r"(r0), "=r"(r1), "=r"(r2), "=r"(r3) : "r"(addr));
}
__device__ __forceinline__ void mma16816(float* c, const uint32_t* a, const uint32_t* b) {
    asm volatile(
        "mma.sync.aligned.m16n8k16.row.col.f32.bf16.bf16.f32 "
        "{%0,%1,%2,%3}, {%4,%5,%6,%7}, {%8,%9}, {%0,%1,%2,%3};"
        : "+f"(c[0]), "+f"(c[1]), "+f"(c[2]), "+f"(c[3])
        : "r"(a[0]), "r"(a[1]), "r"(a[2]), "r"(a[3]), "r"(b[0]), "r"(b[1]));
}
__device__ __forceinline__ float ex2(float x) {
    float r;
    asm("ex2.approx.ftz.f32 %0, %1;" : "=f"(r) : "f"(x));
    return r;
}
__device__ __forceinline__ void split2(float x, float y, uint32_t& hi, uint32_t& lo) {
    bf16 hx = __float2bfloat16_rn(x);
    bf16 hy = __float2bfloat16_rn(y);
    bf16 lx = __float2bfloat16_rn(x - __bfloat162float(hx));
    bf16 ly = __float2bfloat16_rn(y - __bfloat162float(hy));
    __nv_bfloat162 H = {hx, hy}, L = {lx, ly};
    hi = *reinterpret_cast<uint32_t*>(&H);
    lo = *reinterpret_cast<uint32_t*>(&L);
}
__device__ __forceinline__ void cp16(uint32_t smem_dst, const void* gsrc) {
    asm volatile("cp.async.cg.shared.global [%0], [%1], 16;"
                 :: "r"(smem_dst), "l"(gsrc) : "memory");
}
#define CP_COMMIT() asm volatile("cp.async.commit_group;" ::: "memory")
#define CP_WAIT0()  asm volatile("cp.async.wait_group 0;" ::: "memory")

// ============================================================================
// fp32 -> bf16 hi/lo, panel-major: plane[p*R*32 + r*32 + (k&31)], p = k>>5
// ============================================================================
__global__ __launch_bounds__(256) void convert_split(const float* __restrict__ src,
                                                     bf16* __restrict__ H,
                                                     bf16* __restrict__ L, int R)
{
    int idx = blockIdx.x * blockDim.x + threadIdx.x;
    if (idx >= R * 1024) return;
    int r = idx >> 10;
    int k4 = (idx & 1023) * 4;
    float4 v = *(const float4*)(src + (size_t)r * 4096 + k4);
    size_t off = (size_t)(k4 >> 5) * R * 32 + (size_t)r * 32 + (k4 & 31);
    uint32_t h0, l0, h1, l1;
    split2(v.x, v.y, h0, l0);
    split2(v.z, v.w, h1, l1);
    *(uint2*)(H + off) = make_uint2(h0, h1);
    *(uint2*)(L + off) = make_uint2(l0, l1);
}

// ============================================================================
// cp.async double-buffered bf16 split GEMM (R9-measured-best core).
// ============================================================================
#define PLSZ   10240
#define STAGESZ (4 * PLSZ)
#define GPIPE_SMEM (2 * STAGESZ)

__device__ __forceinline__ void gemm_core(
    const bf16* __restrict__ Ahp, const bf16* __restrict__ Alp, int RA,
    const bf16* __restrict__ Bhp, const bf16* __restrict__ Blp, int RB,
    float* __restrict__ C, int Cs, int m0, int n0, char* sm)
{
    const uint32_t sb = smem_u32(sm);
    const int tid = threadIdx.x, lane = tid & 31, wid = tid >> 5;
    const int wr = wid >> 1, wc = wid & 1;

    const bf16* cur[8];
    uint32_t smoff[8];
    size_t pstr[8];
    {
        const bf16* gbase[4] = {Ahp + (size_t)m0 * 32, Alp + (size_t)m0 * 32,
                                Bhp + (size_t)n0 * 32, Blp + (size_t)n0 * 32};
        const size_t pstride[4] = {(size_t)RA * 32, (size_t)RA * 32,
                                   (size_t)RB * 32, (size_t)RB * 32};
#pragma unroll
        for (int j = 0; j < 8; j++) {
            int p = j >> 1;
            int cip = tid + 256 * (j & 1);
            cur[j] = gbase[p] + cip * 8;
            pstr[j] = pstride[p];
            smoff[j] = p * PLSZ + (cip >> 2) * 80 + (cip & 3) * 16;
        }
    }

    const uint32_t aA = sb + (wr * 32 + (lane & 15)) * 80 + ((lane >> 4) & 1) * 16;
    const uint32_t aB = sb + 2 * PLSZ +
        (wc * 64 + (lane & 7) + ((lane >> 4) & 1) * 8) * 80 + ((lane >> 3) & 1) * 16;

    float acc[2][8][4];
#pragma unroll
    for (int mt = 0; mt < 2; mt++)
#pragma unroll
        for (int nt = 0; nt < 8; nt++)
#pragma unroll
            for (int i = 0; i < 4; i++) acc[mt][nt][i] = 0.f;

#pragma unroll
    for (int j = 0; j < 8; j++) { cp16(sb + smoff[j], cur[j]); cur[j] += pstr[j]; }
    CP_COMMIT();

    const int NK = 128;
    for (int it = 0; it < NK; ++it) {
        const uint32_t stg = (uint32_t)(it & 1) * STAGESZ;
        CP_WAIT0();
        __syncthreads();
        if (it + 1 < NK) {
            const uint32_t nstg = (uint32_t)((it + 1) & 1) * STAGESZ;
#pragma unroll
            for (int j = 0; j < 8; j++) { cp16(sb + nstg + smoff[j], cur[j]); cur[j] += pstr[j]; }
            CP_COMMIT();
        }

#pragma unroll
        for (int ks = 0; ks < 2; ks++) {
            const uint32_t ko = stg + ks * 32;
            uint32_t Ah[2][4], Al[2][4];
#pragma unroll
            for (int mt = 0; mt < 2; mt++) {
                ldmx4(Ah[mt][0], Ah[mt][1], Ah[mt][2], Ah[mt][3], aA + ko + mt * 16 * 80);
                ldmx4(Al[mt][0], Al[mt][1], Al[mt][2], Al[mt][3],
                      aA + ko + PLSZ + mt * 16 * 80);
            }
#pragma unroll
            for (int np = 0; np < 4; np++) {
                uint32_t Bh[4], Bl[4];
                ldmx4(Bh[0], Bh[1], Bh[2], Bh[3], aB + ko + np * 16 * 80);
                ldmx4(Bl[0], Bl[1], Bl[2], Bl[3], aB + ko + PLSZ + np * 16 * 80);
#pragma unroll
                for (int mt = 0; mt < 2; mt++) {
                    mma16816(acc[mt][2*np],   Ah[mt], Bh);
                    mma16816(acc[mt][2*np],   Ah[mt], Bl);
                    mma16816(acc[mt][2*np],   Al[mt], Bh);
                    mma16816(acc[mt][2*np+1], Ah[mt], Bh + 2);
                    mma16816(acc[mt][2*np+1], Ah[mt], Bl + 2);
                    mma16816(acc[mt][2*np+1], Al[mt], Bh + 2);
                }
            }
        }
    }

    const int gid = lane >> 2, tig = lane & 3;
#pragma unroll
    for (int mt = 0; mt < 2; mt++) {
        const int row = m0 + wr * 32 + mt * 16 + gid;
#pragma unroll
        for (int nt = 0; nt < 8; nt++) {
            const int col = n0 + wc * 64 + nt * 8 + tig * 2;
            *(float2*)(C + (size_t)row * Cs + col) =
                make_float2(acc[mt][nt][0], acc[mt][nt][1]);
            *(float2*)(C + (size_t)(row + 8) * Cs + col) =
                make_float2(acc[mt][nt][2], acc[mt][nt][3]);
        }
    }
}

__global__ __launch_bounds__(256, 2) void gemm_qkv(float* __restrict__ qo,
                                                   float* __restrict__ ko,
                                                   float* __restrict__ vo)
{
    extern __shared__ char sm[];
    const int bx = blockIdx.x, by = blockIdx.y;
    const bf16 *Bh, *Bl; float* C; int Cs, RB, nb;
    if (bx < 32)      { Bh = g_wqh; Bl = g_wql; C = qo; Cs = 4096; RB = 4096; nb = bx; }
    else if (bx < 40) { Bh = g_wkh; Bl = g_wkl; C = ko; Cs = 1024; RB = 1024; nb = bx - 32; }
    else              { Bh = g_wvh; Bl = g_wvl; C = vo; Cs = 1024; RB = 1024; nb = bx - 40; }
    gemm_core(g_xh, g_xl, 2048, Bh, Bl, RB, C, Cs, by * 128, nb * 128, sm);
}

__global__ __launch_bounds__(256, 2) void gemm_wo(float* __restrict__ out)
{
    extern __shared__ char sm[];
    gemm_core(g_oh, g_ol, 2048, g_woh, g_wol, 4096, out, 4096,
              blockIdx.y * 128, blockIdx.x * 128, sm);
}

// ---------------------------------------------------------------------------
// RoPE table: pow hoisted to smem (64 per block instead of per element);
// fp64 angle + fmod range-reduce, fp32 sincos. Table delta vs fp64 ~2e-7 abs.
// ---------------------------------------------------------------------------
__global__ void rope_table()
{
    __shared__ double sinv[64];
    if (threadIdx.x < 64)
        sinv[threadIdx.x] = pow(500000.0, -(double)threadIdx.x / 64.0);
    __syncthreads();
    int idx = blockIdx.x * blockDim.x + threadIdx.x;
    if (idx >= S_LEN * 64) return;
    int s = idx >> 6, i = idx & 63;
    double a = fmod((double)s * sinv[i], 6.283185307179586476925286766559);
    float fa = (float)a;
    float sn, cs;
    __sincosf(fa, &sn, &cs);
    // __sincosf is fast-math; use precise sinf/cosf instead for accuracy
    cs = cosf(fa);
    sn = sinf(fa);
    g_cos[idx] = cs;
    g_sin[idx] = sn;
}

__global__ void rope_apply(float* __restrict__ buf, int nheads)
{
    int idx = blockIdx.x * blockDim.x + threadIdx.x;
    int total = S_LEN * nheads * 64;
    if (idx >= total) return;
    int i = idx & 63;
    int h = (idx >> 6) % nheads;
    int s = idx / (nheads * 64);
    float c  = g_cos[s * 64 + i];
    float sn = g_sin[s * 64 + i];
    float* p = buf + (size_t)s * nheads * HEADD + h * HEADD;
    float x0 = p[i];
    float x1 = p[i + 64];
    p[i]      = x0 * c - x1 * sn;
    p[i + 64] = x1 * c + x0 * sn;
}

// ============================================================================
// kv_prep: K (RoPE'd) + V -> bf16 hi/lo smem-image tiles in gmem.
// ============================================================================
__global__ __launch_bounds__(256) void kv_prep()
{
    int t = blockIdx.x * 256 + threadIdx.x;
    int q = t & 3, kvh = (t >> 2) & 7, s = t >> 5;
    const float* kp = g_k + (size_t)s * KVDIM + kvh * HEADD + q * 32;
    const float* pp = g_k + (size_t)s * KVDIM + kvh * HEADD + (q ^ 2) * 32;
    const float* vp = g_v + (size_t)s * KVDIM + kvh * HEADD + q * 32;
    const float* cp_ = g_cos + (size_t)s * 64 + (q & 1) * 32;
    const float* sp_ = g_sin + (size_t)s * 64 + (q & 1) * 32;
    const float sgn = (q < 2) ? -1.f : 1.f;
    const int j = s >> 6, r = s & 63;
    char* tb = (char*)g_kvt + (size_t)(kvh * 32 + j) * TILESZ + r * 272 + q * 64;
    char* kh = tb;
    char* kl = tb + PL;
    char* vh = tb + 2 * PL;
    char* vl = tb + 3 * PL;
#pragma unroll
    for (int c = 0; c < 8; c++) {
        float4 x  = ((const float4*)kp)[c];
        float4 px = ((const float4*)pp)[c];
        float4 cc = ((const float4*)cp_)[c];
        float4 sv = ((const float4*)sp_)[c];
        x.x = x.x * cc.x + sgn * px.x * sv.x;
        x.y = x.y * cc.y + sgn * px.y * sv.y;
        x.z = x.z * cc.z + sgn * px.z * sv.z;
        x.w = x.w * cc.w + sgn * px.w * sv.w;
        uint32_t h0, l0, h1, l1;
        split2(x.x, x.y, h0, l0);
        split2(x.z, x.w, h1, l1);
        ((uint2*)kh)[c] = make_uint2(h0, h1);
        ((uint2*)kl)[c] = make_uint2(l0, l1);
        x = ((const float4*)vp)[c];
        split2(x.x, x.y, h0, l0);
        split2(x.z, x.w, h1, l1);
        ((uint2*)vh)[c] = make_uint2(h0, h1);
        ((uint2*)vl)[c] = make_uint2(l0, l1);
    }
}

// ============================================================================
// Tensor-core flash attention: Q fp32 load+scale+split, KV via cp.async
// double-buffer from pre-formatted tiles. (R11-validated)
// ============================================================================
#define FQHo 0
#define FQLo 34816
#define SKV0 69632
#define FA3_SMEM (69632 + 2 * TILESZ)    // 208896

__global__ __launch_bounds__(256) void flash_mma(const float* __restrict__ Q,
                                                 float* __restrict__ O)
{
    extern __shared__ char sm[];
    const uint32_t sb = smem_u32(sm);
    const int tid = threadIdx.x, lane = tid & 31, wid = tid >> 5;
    const int h = blockIdx.y;
    const int bxr = (int)gridDim.x - 1 - (int)blockIdx.x;   // heavy blocks first
    const int m0 = bxr * 128;
    const int kvh = h >> 2;
    const float qscale = 0.0883883476483184f * 1.4426950408889634f;

    {
        int row = tid >> 1, half = tid & 1;
        const float* qp = Q + (size_t)(m0 + row) * HDIM + h * HEADD + half * 64;
        char* dh = sm + FQHo + row * 272 + half * 128;
        char* dl = sm + FQLo + row * 272 + half * 128;
#pragma unroll
        for (int c = 0; c < 16; c++) {
            float4 v = ((const float4*)qp)[c];
            v.x *= qscale; v.y *= qscale; v.z *= qscale; v.w *= qscale;
            uint32_t h0, l0, h1, l1;
            split2(v.x, v.y, h0, l0);
            split2(v.z, v.w, h1, l1);
            ((uint2*)dh)[c] = make_uint2(h0, h1);
            ((uint2*)dl)[c] = make_uint2(l0, l1);
        }
    }

    float o[16][4];
#pragma unroll
    for (int dt = 0; dt < 16; dt++)
#pragma unroll
        for (int i = 0; i < 4; i++) o[dt][i] = 0.f;
    float mA = -1e30f, mB = -1e30f, lA = 0.f, lB = 0.f;

    const int wrow0 = m0 + wid * 16;
    const uint32_t aQh = sb + FQHo + (wid * 16 + (lane & 15)) * 272 + ((lane >> 4) & 1) * 16;
    const uint32_t aQl = aQh + (FQLo - FQHo);
    const uint32_t relK = ((lane & 7) + ((lane >> 4) & 1) * 8) * 272 + ((lane >> 3) & 1) * 16;
    const uint32_t relV = ((lane & 7) + ((lane >> 3) & 1) * 8) * 272 + ((lane >> 4) & 1) * 16;

    const char* blob = (const char*)g_kvt + (size_t)(kvh * 32) * TILESZ;
    const int jmax = 2 * bxr + 1;

    {
        const char* src = blob + tid * 16;
        const uint32_t dst = sb + SKV0 + tid * 16;
#pragma unroll
        for (int i = 0; i < 17; i++) cp16(dst + i * 4096, src + i * 4096);
        CP_COMMIT();
    }

    for (int j = 0; j <= jmax; j++) {
        const int n0 = j * 64;
        const uint32_t stg = SKV0 + (uint32_t)(j & 1) * TILESZ;
        CP_WAIT0();
        __syncthreads();
        if (j + 1 <= jmax) {
            const char* src = blob + (size_t)(j + 1) * TILESZ + tid * 16;
            const uint32_t dst = sb + SKV0 + (uint32_t)((j + 1) & 1) * TILESZ + tid * 16;
#pragma unroll
            for (int i = 0; i < 17; i++) cp16(dst + i * 4096, src + i * 4096);
            CP_COMMIT();
        }

        if (n0 > wrow0 + 15) continue;

        const uint32_t aKh = sb + stg + relK;
        const uint32_t aKl = aKh + PL;
        const uint32_t aVh = sb + stg + 2 * PL + relV;
        const uint32_t aVl = aVh + PL;

        float s[8][4];
#pragma unroll
        for (int t = 0; t < 8; t++)
#pragma unroll
            for (int i = 0; i < 4; i++) s[t][i] = 0.f;

#pragma unroll
        for (int kc = 0; kc < 8; kc++) {
            uint32_t qh[4], ql[4];
            ldmx4(qh[0], qh[1], qh[2], qh[3], aQh + kc * 32);
            ldmx4(ql[0], ql[1], ql[2], ql[3], aQl + kc * 32);
#pragma unroll
            for (int np = 0; np < 4; np++) {
                uint32_t kh[4], kl[4];
                ldmx4(kh[0], kh[1], kh[2], kh[3], aKh + np * 16 * 272 + kc * 32);
                ldmx4(kl[0], kl[1], kl[2], kl[3], aKl + np * 16 * 272 + kc * 32);
                mma16816(s[2*np],   qh, kh);
                mma16816(s[2*np],   qh, kl);
                mma16816(s[2*np],   ql, kh);
                mma16816(s[2*np+1], qh, kh + 2);
                mma16816(s[2*np+1], qh, kl + 2);
                mma16816(s[2*np+1], ql, kh + 2);
            }
        }

        const int rA = wrow0 + (lane >> 2);
        const int rB = rA + 8;
        const int cb = n0 + 2 * (lane & 3);
        if (n0 + 63 > wrow0) {
#pragma unroll
            for (int t = 0; t < 8; t++) {
                int c0 = cb + 8 * t;
                if (c0     > rA) s[t][0] = -1e30f;
                if (c0 + 1 > rA) s[t][1] = -1e30f;
                if (c0     > rB) s[t][2] = -1e30f;
                if (c0 + 1 > rB) s[t][3] = -1e30f;
            }
        }

        float xA = -1e30f, xB = -1e30f;
#pragma unroll
        for (int t = 0; t < 8; t++) {
            xA = fmaxf(xA, fmaxf(s[t][0], s[t][1]));
            xB = fmaxf(xB, fmaxf(s[t][2], s[t][3]));
        }
        xA = fmaxf(xA, __shfl_xor_sync(0xffffffffu, xA, 1));
        xA = fmaxf(xA, __shfl_xor_sync(0xffffffffu, xA, 2));
        xB = fmaxf(xB, __shfl_xor_sync(0xffffffffu, xB, 1));
        xB = fmaxf(xB, __shfl_xor_sync(0xffffffffu, xB, 2));
        float mAn = fmaxf(mA, xA), mBn = fmaxf(mB, xB);
        float cA = ex2(mA - mAn), cB = ex2(mB - mBn);
        mA = mAn; mB = mBn;
        float sumA = 0.f, sumB = 0.f;
#pragma unroll
        for (int t = 0; t < 8; t++) {
            s[t][0] = ex2(s[t][0] - mA); sumA += s[t][0];
            s[t][1] = ex2(s[t][1] - mA); sumA += s[t][1];
            s[t][2] = ex2(s[t][2] - mB); sumB += s[t][2];
            s[t][3] = ex2(s[t][3] - mB); sumB += s[t][3];
        }
        sumA += __shfl_xor_sync(0xffffffffu, sumA, 1);
        sumA += __shfl_xor_sync(0xffffffffu, sumA, 2);
        sumB += __shfl_xor_sync(0xffffffffu, sumB, 1);
        sumB += __shfl_xor_sync(0xffffffffu, sumB, 2);
        lA = lA * cA + sumA;
        lB = lB * cB + sumB;
#pragma unroll
        for (int dt = 0; dt < 16; dt++) {
            o[dt][0] *= cA; o[dt][1] *= cA;
            o[dt][2] *= cB; o[dt][3] *= cB;
        }

#pragma unroll
        for (int kc = 0; kc < 4; kc++) {
            uint32_t ph[4], pl[4];
            split2(s[2*kc][0],   s[2*kc][1],   ph[0], pl[0]);
            split2(s[2*kc][2],   s[2*kc][3],   ph[1], pl[1]);
            split2(s[2*kc+1][0], s[2*kc+1][1], ph[2], pl[2]);
            split2(s[2*kc+1][2], s[2*kc+1][3], ph[3], pl[3]);
#pragma unroll
            for (int dp = 0; dp < 8; dp++) {
                uint32_t vh[4], vl[4];
                ldmx4t(vh[0], vh[1], vh[2], vh[3], aVh + kc * 16 * 272 + dp * 32);
                ldmx4t(vl[0], vl[1], vl[2], vl[3], aVl + kc * 16 * 272 + dp * 32);
                mma16816(o[2*dp],   ph, vh);
                mma16816(o[2*dp],   ph, vl);
                mma16816(o[2*dp],   pl, vh);
                mma16816(o[2*dp+1], ph, vh + 2);
                mma16816(o[2*dp+1], ph, vl + 2);
                mma16816(o[2*dp+1], pl, vh + 2);
            }
        }
    }

    const float ilA = 1.f / lA, ilB = 1.f / lB;
    const int rA = wrow0 + (lane >> 2);
    const int colb = h * HEADD + 2 * (lane & 3);
#pragma unroll
    for (int dt = 0; dt < 16; dt++) {
        *(float2*)(O + (size_t)rA * HDIM + colb + 8 * dt) =
            make_float2(o[dt][0] * ilA, o[dt][1] * ilA);
        *(float2*)(O + (size_t)(rA + 8) * HDIM + colb + 8 * dt) =
            make_float2(o[dt][2] * ilB, o[dt][3] * ilB);
    }
}

// ---------------------------------------------------------------------------
extern "C" void kernel_launch(void* const* d_in, const int* in_sizes, int n_in,
                              void* d_out, int out_size)
{
    const float* x  = (const float*)d_in[0];
    const float* wq = (const float*)d_in[1];
    const float* wk = (const float*)d_in[2];
    const float* wv = (const float*)d_in[3];
    const float* wo = (const float*)d_in[4];
    float* out = (float*)d_out;

    float *qb, *kb, *vb, *ob;
    cudaGetSymbolAddress((void**)&qb, g_q);
    cudaGetSymbolAddress((void**)&kb, g_k);
    cudaGetSymbolAddress((void**)&vb, g_v);
    cudaGetSymbolAddress((void**)&ob, g_o);
    bf16 *xh, *xl, *wqh, *wql, *wkh, *wkl, *wvh, *wvl, *woh, *wol, *oh, *ol;
    cudaGetSymbolAddress((void**)&xh,  g_xh);  cudaGetSymbolAddress((void**)&xl,  g_xl);
    cudaGetSymbolAddress((void**)&wqh, g_wqh); cudaGetSymbolAddress((void**)&wql, g_wql);
    cudaGetSymbolAddress((void**)&wkh, g_wkh); cudaGetSymbolAddress((void**)&wkl, g_wkl);
    cudaGetSymbolAddress((void**)&wvh, g_wvh); cudaGetSymbolAddress((void**)&wvl, g_wvl);
    cudaGetSymbolAddress((void**)&woh, g_woh); cudaGetSymbolAddress((void**)&wol, g_wol);
    cudaGetSymbolAddress((void**)&oh,  g_oh);  cudaGetSymbolAddress((void**)&ol,  g_ol);

    cudaFuncSetAttribute(flash_mma, cudaFuncAttributeMaxDynamicSharedMemorySize, FA3_SMEM);
    cudaFuncSetAttribute(gemm_qkv,  cudaFuncAttributeMaxDynamicSharedMemorySize, GPIPE_SMEM);
    cudaFuncSetAttribute(gemm_wo,   cudaFuncAttributeMaxDynamicSharedMemorySize, GPIPE_SMEM);

    // Launch order arranged so gemm_qkv is the 6th launch (ncu -s 5 -c 1
    // profiles it next round). conv(wo) moved after gemm_qkv — only gemm_wo
    // depends on it.
    rope_table<<<(S_LEN * 64) / 256, 256>>>();                        // 1
    convert_split<<<(2048 * 1024) / 256, 256>>>(x,  xh,  xl,  2048);  // 2
    convert_split<<<(4096 * 1024) / 256, 256>>>(wq, wqh, wql, 4096);  // 3
    convert_split<<<(1024 * 1024) / 256, 256>>>(wk, wkh, wkl, 1024);  // 4
    convert_split<<<(1024 * 1024) / 256, 256>>>(wv, wvh, wvl, 1024);  // 5

    gemm_qkv<<<dim3(48, 16), 256, GPIPE_SMEM>>>(qb, kb, vb);          // 6 <- profiled

    convert_split<<<(4096 * 1024) / 256, 256>>>(wo, woh, wol, 4096);  // 7
    rope_apply<<<(S_LEN * NHEADS * 64) / 256, 256>>>(qb, NHEADS);     // 8
    kv_prep<<<256, 256>>>();                                          // 9
    flash_mma<<<dim3(S_LEN / 128, NHEADS), 256, FA3_SMEM>>>(qb, ob);  // 10
    convert_split<<<(2048 * 1024) / 256, 256>>>(ob, oh, ol, 2048);    // 11
    gemm_wo<<<dim3(32, 16), 256, GPIPE_SMEM>>>(out);                  // 12
}